// round 1
// baseline (speedup 1.0000x reference)
#include <cuda_runtime.h>
#include <math.h>

#define NB 128
#define NT 1024
#define TILE 32
#define PAD 36

// per-batch modulation base: code@ltm_w[0:128] + dir_emb@ltm_w[288:296] + ltm_b
__device__ float g_base[NB * 512];

__device__ __forceinline__ unsigned long long pack2(float x) {
    unsigned long long r;
    asm("mov.b64 %0, {%1, %1};" : "=l"(r) : "f"(x));
    return r;
}
__device__ __forceinline__ float2 unpack2(unsigned long long v) {
    float2 r;
    asm("mov.b64 {%0, %1}, %2;" : "=f"(r.x), "=f"(r.y) : "l"(v));
    return r;
}
__device__ __forceinline__ void ffma2(unsigned long long& acc, unsigned long long a,
                                      unsigned long long b) {
    asm("fma.rn.f32x2 %0, %1, %2, %0;" : "+l"(acc) : "l"(a), "l"(b));
}

__global__ void base_kernel(const float* __restrict__ code,
                            const int* __restrict__ dir_idx,
                            const float* __restrict__ dir_emb,
                            const float* __restrict__ ltm_w,
                            const float* __restrict__ ltm_b) {
    int b = blockIdx.x, j = threadIdx.x;  // 128 blocks x 512 threads
    float acc = ltm_b[j];
    const float* c = code + b * 128;
#pragma unroll 4
    for (int k = 0; k < 128; k++) acc = fmaf(c[k], ltm_w[k * 512 + j], acc);
    const float* dv = dir_emb + dir_idx[b] * 8;
#pragma unroll
    for (int k = 0; k < 8; k++) acc = fmaf(dv[k], ltm_w[(288 + k) * 512 + j], acc);
    g_base[b * 512 + j] = acc;
}

__global__ __launch_bounds__(256, 2) void fused_kernel(
    const float* __restrict__ coords, const float* __restrict__ hs,
    const float* __restrict__ xstat,
    const float* __restrict__ se_w1, const float* __restrict__ se_b1,
    const float* __restrict__ se_w2, const float* __restrict__ se_b2,
    const float* __restrict__ ltm_w,
    const float* __restrict__ l0_w, const float* __restrict__ l0_b,
    const float* __restrict__ l1_w, const float* __restrict__ l1_b,
    const float* __restrict__ l2_w, const float* __restrict__ l2_b,
    float* __restrict__ out)
{
    extern __shared__ float sh[];
    float* hsT   = sh;                   // [128][PAD]  hs tile, transposed [k][t]
    float* spT   = hsT + 128 * PAD;      // [32][PAD]   spatial, transposed
    float* posT  = spT + 32 * PAD;       // [16][PAD]   pos enc, transposed
    float* x0T   = posT + 16 * PAD;      // [256][PAD]  layer0 activations [j][t]
    float* hbuf  = x0T + 256 * PAD;      // [32][32]    gelu hidden
    float* baseb = hbuf + 32 * 32;       // [512]       per-batch base

    const int b = blockIdx.y;
    const int t0 = blockIdx.x * TILE;
    const int tid = threadIdx.x;

    // ---- Phase A: stage tile inputs ----
    const float* hs_g = hs + ((size_t)b * NT + t0) * 128;
#pragma unroll
    for (int i = 0; i < 16; i++) {
        int idx = tid + i * 256;                       // 0..4095
        hsT[(idx & 127) * PAD + (idx >> 7)] = hs_g[idx];
    }
    baseb[tid]       = g_base[b * 512 + tid];
    baseb[256 + tid] = g_base[b * 512 + 256 + tid];

    const float* crd = coords + (size_t)b * NT + t0;
#pragma unroll
    for (int i = 0; i < 2; i++) {
        int idx = tid + i * 256;                       // 0..511
        int t = idx & 31, v = idx >> 5;                // v in 0..15
        float val = crd[t] * (1.25f * (float)(v & 7));
        posT[v * PAD + t] = (v < 8) ? sinf(val) : cosf(val);
    }
    const float* xs_g = xstat + ((size_t)b * NT + t0) * 4;
#pragma unroll
    for (int i = 0; i < 4; i++) {
        int idx = tid + i * 256;                       // 0..1023
        int t = idx >> 5, c = idx & 31;
        float a = se_b1[c];
#pragma unroll
        for (int q = 0; q < 4; q++) a = fmaf(xs_g[t * 4 + q], se_w1[q * 32 + c], a);
        hbuf[t * 32 + c] = 0.5f * a * (1.0f + erff(a * 0.7071067811865476f));  // exact gelu
    }
    __syncthreads();
#pragma unroll
    for (int i = 0; i < 4; i++) {
        int idx = tid + i * 256;
        int t = idx >> 5, k = idx & 31;
        float a = se_b2[k];
#pragma unroll
        for (int c = 0; c < 32; c++) a = fmaf(hbuf[t * 32 + c], se_w2[c * 32 + k], a);
        spT[k * PAD + t] = a;
    }
    __syncthreads();

    // ---- Phase B: thread j owns mod channels j and j+256 across 32 timesteps ----
    const int j = tid;
    unsigned long long acc0[16], acc1[16];
    {
        unsigned long long i0 = pack2(baseb[j] + l0_b[j]);        // fold biases into init
        unsigned long long i1 = pack2(baseb[256 + j] + l1_b[j]);
#pragma unroll
        for (int i = 0; i < 16; i++) { acc0[i] = i0; acc1[i] = i1; }
    }

    // hs contribution: ltm_w rows 128..255
    const float* Wh = ltm_w + 128 * 512;
#pragma unroll 4
    for (int k = 0; k < 128; k++) {
        unsigned long long w0 = pack2(Wh[k * 512 + j]);
        unsigned long long w1 = pack2(Wh[k * 512 + 256 + j]);
        const ulonglong2* hp = (const ulonglong2*)(hsT + k * PAD);
#pragma unroll
        for (int q = 0; q < 8; q++) {
            ulonglong2 h = hp[q];
            ffma2(acc0[2 * q], h.x, w0);     ffma2(acc0[2 * q + 1], h.y, w0);
            ffma2(acc1[2 * q], h.x, w1);     ffma2(acc1[2 * q + 1], h.y, w1);
        }
    }
    // spatial contribution: ltm_w rows 256..287
    const float* Ws = ltm_w + 256 * 512;
#pragma unroll 4
    for (int k = 0; k < 32; k++) {
        unsigned long long w0 = pack2(Ws[k * 512 + j]);
        unsigned long long w1 = pack2(Ws[k * 512 + 256 + j]);
        const ulonglong2* sp = (const ulonglong2*)(spT + k * PAD);
#pragma unroll
        for (int q = 0; q < 8; q++) {
            ulonglong2 s = sp[q];
            ffma2(acc0[2 * q], s.x, w0);     ffma2(acc0[2 * q + 1], s.y, w0);
            ffma2(acc1[2 * q], s.x, w1);     ffma2(acc1[2 * q + 1], s.y, w1);
        }
    }
    // layer0: pos @ l0_w
#pragma unroll
    for (int v = 0; v < 16; v++) {
        unsigned long long w = pack2(l0_w[v * 256 + j]);
        const ulonglong2* pp = (const ulonglong2*)(posT + v * PAD);
#pragma unroll
        for (int q = 0; q < 8; q++) {
            ulonglong2 p = pp[q];
            ffma2(acc0[2 * q], p.x, w);      ffma2(acc0[2 * q + 1], p.y, w);
        }
    }
    // relu -> x0T[j][t]
#pragma unroll
    for (int i = 0; i < 16; i++) {
        float2 v = unpack2(acc0[i]);
        x0T[j * PAD + 2 * i]     = fmaxf(v.x, 0.0f);
        x0T[j * PAD + 2 * i + 1] = fmaxf(v.y, 0.0f);
    }
    __syncthreads();

    // layer1: x0 @ l1_w (acc1 already holds base1 + mods1 + l1_b)
#pragma unroll 4
    for (int k = 0; k < 256; k++) {
        unsigned long long w = pack2(l1_w[k * 256 + j]);
        const ulonglong2* xp = (const ulonglong2*)(x0T + k * PAD);
#pragma unroll
        for (int q = 0; q < 8; q++) {
            ulonglong2 x = xp[q];
            ffma2(acc1[2 * q], x.x, w);      ffma2(acc1[2 * q + 1], x.y, w);
        }
    }
    // relu and scale by l2_w[j]
    float cr[32];
    {
        float w2 = l2_w[j];
#pragma unroll
        for (int i = 0; i < 16; i++) {
            float2 v = unpack2(acc1[i]);
            cr[2 * i]     = fmaxf(v.x, 0.0f) * w2;
            cr[2 * i + 1] = fmaxf(v.y, 0.0f) * w2;
        }
    }
    __syncthreads();   // everyone done reading x0T before overwrite
#pragma unroll
    for (int t = 0; t < TILE; t++) x0T[j * PAD + t] = cr[t];
    __syncthreads();

    // ---- reduce over 256 channels -> out[b, t0+t] ----
    int warp = tid >> 5, lane = tid & 31;
    float l2b = l2_b[0];
#pragma unroll
    for (int tt = 0; tt < 4; tt++) {
        int t = warp + tt * 8;
        float s = 0.0f;
#pragma unroll
        for (int m = 0; m < 8; m++) s += x0T[(lane + 32 * m) * PAD + t];
#pragma unroll
        for (int off = 16; off; off >>= 1) s += __shfl_down_sync(0xffffffffu, s, off);
        if (lane == 0) out[(size_t)b * NT + t0 + t] = s + l2b;
    }
}

extern "C" void kernel_launch(void* const* d_in, const int* in_sizes, int n_in,
                              void* d_out, int out_size) {
    const float* coords  = (const float*)d_in[0];
    const float* code    = (const float*)d_in[1];
    const float* hs      = (const float*)d_in[2];
    const float* xstat   = (const float*)d_in[3];
    const int*   dir_idx = (const int*)  d_in[4];
    const float* se_w1   = (const float*)d_in[5];
    const float* se_b1   = (const float*)d_in[6];
    const float* se_w2   = (const float*)d_in[7];
    const float* se_b2   = (const float*)d_in[8];
    const float* dir_emb = (const float*)d_in[9];
    const float* ltm_w   = (const float*)d_in[10];
    const float* ltm_b   = (const float*)d_in[11];
    const float* l0_w    = (const float*)d_in[12];
    const float* l0_b    = (const float*)d_in[13];
    const float* l1_w    = (const float*)d_in[14];
    const float* l1_b    = (const float*)d_in[15];
    const float* l2_w    = (const float*)d_in[16];
    const float* l2_b    = (const float*)d_in[17];
    float* out = (float*)d_out;

    const int smem_bytes = (128 * PAD + 32 * PAD + 16 * PAD + 256 * PAD + 32 * 32 + 512) * 4;
    cudaFuncSetAttribute(fused_kernel, cudaFuncAttributeMaxDynamicSharedMemorySize, smem_bytes);

    base_kernel<<<NB, 512>>>(code, dir_idx, dir_emb, ltm_w, ltm_b);

    dim3 grid(NT / TILE, NB);
    fused_kernel<<<grid, 256, smem_bytes>>>(coords, hs, xstat, se_w1, se_b1, se_w2, se_b2,
                                            ltm_w, l0_w, l0_b, l1_w, l1_b, l2_w, l2_b, out);
}

// round 2
// speedup vs baseline: 1.0566x; 1.0566x over previous
#include <cuda_runtime.h>
#include <math.h>

#define NB 128
#define NT 1024
#define TILE 32
#define PAD 36

// per-batch modulation base: code@ltm_w[0:128] + dir_emb@ltm_w[288:296] + ltm_b
__device__ float g_base[NB * 512];

__device__ __forceinline__ unsigned long long pack2(float x) {
    unsigned long long r;
    asm("mov.b64 %0, {%1, %1};" : "=l"(r) : "f"(x));
    return r;
}
__device__ __forceinline__ float2 unpack2(unsigned long long v) {
    float2 r;
    asm("mov.b64 {%0, %1}, %2;" : "=f"(r.x), "=f"(r.y) : "l"(v));
    return r;
}
__device__ __forceinline__ void ffma2(unsigned long long& acc, unsigned long long a,
                                      unsigned long long b) {
    asm("fma.rn.f32x2 %0, %1, %2, %0;" : "+l"(acc) : "l"(a), "l"(b));
}

__global__ void base_kernel(const float* __restrict__ code,
                            const int* __restrict__ dir_idx,
                            const float* __restrict__ dir_emb,
                            const float* __restrict__ ltm_w,
                            const float* __restrict__ ltm_b) {
    int b = blockIdx.x, j = threadIdx.x;  // 128 blocks x 512 threads
    float acc = ltm_b[j];
    const float* c = code + b * 128;
#pragma unroll 4
    for (int k = 0; k < 128; k++) acc = fmaf(c[k], ltm_w[k * 512 + j], acc);
    const float* dv = dir_emb + dir_idx[b] * 8;
#pragma unroll
    for (int k = 0; k < 8; k++) acc = fmaf(dv[k], ltm_w[(288 + k) * 512 + j], acc);
    g_base[b * 512 + j] = acc;
}

__global__ __launch_bounds__(256, 2) void fused_kernel(
    const float* __restrict__ coords, const float* __restrict__ hs,
    const float* __restrict__ xstat,
    const float* __restrict__ se_w1, const float* __restrict__ se_b1,
    const float* __restrict__ se_w2, const float* __restrict__ se_b2,
    const float* __restrict__ ltm_w,
    const float* __restrict__ l0_w, const float* __restrict__ l0_b,
    const float* __restrict__ l1_w, const float* __restrict__ l1_b,
    const float* __restrict__ l2_w, const float* __restrict__ l2_b,
    float* __restrict__ out)
{
    extern __shared__ float sh[];
    float* hsT   = sh;                   // [128][PAD]  hs tile, transposed [k][t]
    float* spT   = hsT + 128 * PAD;      // [32][PAD]   spatial, transposed
    float* posT  = spT + 32 * PAD;       // [16][PAD]   pos enc, transposed
    float* x0T   = posT + 16 * PAD;      // [256][PAD]  layer0 activations [j][t]
    float* hbuf  = x0T + 256 * PAD;      // [32][32]    gelu hidden
    float* baseb = hbuf + 32 * 32;       // [512]       per-batch base

    const int b = blockIdx.y;
    const int t0 = blockIdx.x * TILE;
    const int tid = threadIdx.x;

    // ---- Phase A: stage tile inputs ----
    const float* hs_g = hs + ((size_t)b * NT + t0) * 128;
#pragma unroll
    for (int i = 0; i < 16; i++) {
        int idx = tid + i * 256;                       // 0..4095
        hsT[(idx & 127) * PAD + (idx >> 7)] = hs_g[idx];
    }
    baseb[tid]       = g_base[b * 512 + tid];
    baseb[256 + tid] = g_base[b * 512 + 256 + tid];

    const float* crd = coords + (size_t)b * NT + t0;
#pragma unroll
    for (int i = 0; i < 2; i++) {
        int idx = tid + i * 256;                       // 0..511
        int t = idx & 31, v = idx >> 5;                // v in 0..15
        float val = crd[t] * (1.25f * (float)(v & 7));
        posT[v * PAD + t] = (v < 8) ? sinf(val) : cosf(val);
    }
    const float* xs_g = xstat + ((size_t)b * NT + t0) * 4;
#pragma unroll
    for (int i = 0; i < 4; i++) {
        int idx = tid + i * 256;                       // 0..1023
        int t = idx >> 5, c = idx & 31;
        float a = se_b1[c];
#pragma unroll
        for (int q = 0; q < 4; q++) a = fmaf(xs_g[t * 4 + q], se_w1[q * 32 + c], a);
        hbuf[t * 32 + c] = 0.5f * a * (1.0f + erff(a * 0.7071067811865476f));  // exact gelu
    }
    __syncthreads();
#pragma unroll
    for (int i = 0; i < 4; i++) {
        int idx = tid + i * 256;
        int t = idx >> 5, k = idx & 31;
        float a = se_b2[k];
#pragma unroll
        for (int c = 0; c < 32; c++) a = fmaf(hbuf[t * 32 + c], se_w2[c * 32 + k], a);
        spT[k * PAD + t] = a;
    }
    __syncthreads();

    // ---- Phase B: thread j owns mod channels j and j+256 across 32 timesteps ----
    const int j = tid;
    unsigned long long acc0[16], acc1[16];
    {
        unsigned long long i0 = pack2(baseb[j] + l0_b[j]);        // fold biases into init
        unsigned long long i1 = pack2(baseb[256 + j] + l1_b[j]);
#pragma unroll
        for (int i = 0; i < 16; i++) { acc0[i] = i0; acc1[i] = i1; }
    }

    // hs contribution: ltm_w rows 128..255
    const float* Wh = ltm_w + 128 * 512;
#pragma unroll 4
    for (int k = 0; k < 128; k++) {
        unsigned long long w0 = pack2(Wh[k * 512 + j]);
        unsigned long long w1 = pack2(Wh[k * 512 + 256 + j]);
        const ulonglong2* hp = (const ulonglong2*)(hsT + k * PAD);
#pragma unroll
        for (int q = 0; q < 8; q++) {
            ulonglong2 h = hp[q];
            ffma2(acc0[2 * q], h.x, w0);     ffma2(acc0[2 * q + 1], h.y, w0);
            ffma2(acc1[2 * q], h.x, w1);     ffma2(acc1[2 * q + 1], h.y, w1);
        }
    }
    // spatial contribution: ltm_w rows 256..287
    const float* Ws = ltm_w + 256 * 512;
#pragma unroll 4
    for (int k = 0; k < 32; k++) {
        unsigned long long w0 = pack2(Ws[k * 512 + j]);
        unsigned long long w1 = pack2(Ws[k * 512 + 256 + j]);
        const ulonglong2* sp = (const ulonglong2*)(spT + k * PAD);
#pragma unroll
        for (int q = 0; q < 8; q++) {
            ulonglong2 s = sp[q];
            ffma2(acc0[2 * q], s.x, w0);     ffma2(acc0[2 * q + 1], s.y, w0);
            ffma2(acc1[2 * q], s.x, w1);     ffma2(acc1[2 * q + 1], s.y, w1);
        }
    }
    // layer0: pos @ l0_w
#pragma unroll
    for (int v = 0; v < 16; v++) {
        unsigned long long w = pack2(l0_w[v * 256 + j]);
        const ulonglong2* pp = (const ulonglong2*)(posT + v * PAD);
#pragma unroll
        for (int q = 0; q < 8; q++) {
            ulonglong2 p = pp[q];
            ffma2(acc0[2 * q], p.x, w);      ffma2(acc0[2 * q + 1], p.y, w);
        }
    }
    // relu -> x0T[j][t]
#pragma unroll
    for (int i = 0; i < 16; i++) {
        float2 v = unpack2(acc0[i]);
        x0T[j * PAD + 2 * i]     = fmaxf(v.x, 0.0f);
        x0T[j * PAD + 2 * i + 1] = fmaxf(v.y, 0.0f);
    }
    __syncthreads();

    // layer1: x0 @ l1_w (acc1 already holds base1 + mods1 + l1_b)
#pragma unroll 4
    for (int k = 0; k < 256; k++) {
        unsigned long long w = pack2(l1_w[k * 256 + j]);
        const ulonglong2* xp = (const ulonglong2*)(x0T + k * PAD);
#pragma unroll
        for (int q = 0; q < 8; q++) {
            ulonglong2 x = xp[q];
            ffma2(acc1[2 * q], x.x, w);      ffma2(acc1[2 * q + 1], x.y, w);
        }
    }
    // relu and scale by l2_w[j]
    float cr[32];
    {
        float w2 = l2_w[j];
#pragma unroll
        for (int i = 0; i < 16; i++) {
            float2 v = unpack2(acc1[i]);
            cr[2 * i]     = fmaxf(v.x, 0.0f) * w2;
            cr[2 * i + 1] = fmaxf(v.y, 0.0f) * w2;
        }
    }
    __syncthreads();   // everyone done reading x0T before overwrite
#pragma unroll
    for (int t = 0; t < TILE; t++) x0T[j * PAD + t] = cr[t];
    __syncthreads();

    // ---- reduce over 256 channels -> out[b, t0+t] ----
    int warp = tid >> 5, lane = tid & 31;
    float l2b = l2_b[0];
#pragma unroll
    for (int tt = 0; tt < 4; tt++) {
        int t = warp + tt * 8;
        float s = 0.0f;
#pragma unroll
        for (int m = 0; m < 8; m++) s += x0T[(lane + 32 * m) * PAD + t];
#pragma unroll
        for (int off = 16; off; off >>= 1) s += __shfl_down_sync(0xffffffffu, s, off);
        if (lane == 0) out[(size_t)b * NT + t0 + t] = s + l2b;
    }
}

extern "C" void kernel_launch(void* const* d_in, const int* in_sizes, int n_in,
                              void* d_out, int out_size) {
    const float* coords  = (const float*)d_in[0];
    const float* code    = (const float*)d_in[1];
    const float* hs      = (const float*)d_in[2];
    const float* xstat   = (const float*)d_in[3];
    const int*   dir_idx = (const int*)  d_in[4];
    const float* se_w1   = (const float*)d_in[5];
    const float* se_b1   = (const float*)d_in[6];
    const float* se_w2   = (const float*)d_in[7];
    const float* se_b2   = (const float*)d_in[8];
    const float* dir_emb = (const float*)d_in[9];
    const float* ltm_w   = (const float*)d_in[10];
    const float* ltm_b   = (const float*)d_in[11];
    const float* l0_w    = (const float*)d_in[12];
    const float* l0_b    = (const float*)d_in[13];
    const float* l1_w    = (const float*)d_in[14];
    const float* l1_b    = (const float*)d_in[15];
    const float* l2_w    = (const float*)d_in[16];
    const float* l2_b    = (const float*)d_in[17];
    float* out = (float*)d_out;

    const int smem_bytes = (128 * PAD + 32 * PAD + 16 * PAD + 256 * PAD + 32 * 32 + 512) * 4;
    cudaFuncSetAttribute(fused_kernel, cudaFuncAttributeMaxDynamicSharedMemorySize, smem_bytes);

    base_kernel<<<NB, 512>>>(code, dir_idx, dir_emb, ltm_w, ltm_b);

    dim3 grid(NT / TILE, NB);
    fused_kernel<<<grid, 256, smem_bytes>>>(coords, hs, xstat, se_w1, se_b1, se_w2, se_b2,
                                            ltm_w, l0_w, l0_b, l1_w, l1_b, l2_w, l2_b, out);
}

// round 4
// speedup vs baseline: 3.8049x; 3.6011x over previous
#include <cuda_runtime.h>
#include <cuda_fp16.h>
#include <math.h>
#include <stdint.h>

// ---- smem byte offsets ----
#define A_HI   0               // [128][184] fp16, k=0..175 used
#define A_LO   47104
#define WBUF   94208           // 2 x 23552 : W1 chunks [64n][184k] fp16
#define W2BUF  0               // 2 x 33792 : W2 chunks [64n][264k] fp16 (alias A, used after G1)
#define X0OFF  141312          // [128][264] fp16
#define BIAS0  208896
#define BIAS1  209920
#define L2WS   210944
#define SMEMSZ 211968

__device__ float g_base[128 * 512];
__device__ __align__(16) __half g_W1[512 * 176];   // n-major, k = [hs 0..127 | sp 128..159 | pos 160..175]
__device__ __align__(16) __half g_W2[256 * 256];   // n-major

// ---------------- helpers ----------------
__device__ __forceinline__ uint32_t smem_u32(const void* p) {
    uint32_t a;
    asm("{ .reg .u64 t; cvta.to.shared.u64 t, %1; cvt.u32.u64 %0, t; }" : "=r"(a) : "l"(p));
    return a;
}
#define CP16(dst, src) asm volatile("cp.async.cg.shared.global [%0], [%1], 16;" :: "r"(dst), "l"(src))
#define CPCOMMIT()     asm volatile("cp.async.commit_group;")
#define CPWAIT(n)      asm volatile("cp.async.wait_group %0;" :: "n"(n))

__device__ __forceinline__ void ldsm4(uint32_t& r0, uint32_t& r1, uint32_t& r2, uint32_t& r3, uint32_t a) {
    asm volatile("ldmatrix.sync.aligned.m8n8.x4.shared.b16 {%0,%1,%2,%3}, [%4];"
                 : "=r"(r0), "=r"(r1), "=r"(r2), "=r"(r3) : "r"(a));
}
#define MMA(c, A0, A1, A2, A3, B0, B1)                                      \
    asm volatile("mma.sync.aligned.m16n8k16.row.col.f32.f16.f16.f32 "       \
                 "{%0,%1,%2,%3}, {%4,%5,%6,%7}, {%8,%9}, {%0,%1,%2,%3};"    \
                 : "+f"((c)[0]), "+f"((c)[1]), "+f"((c)[2]), "+f"((c)[3])   \
                 : "r"(A0), "r"(A1), "r"(A2), "r"(A3), "r"(B0), "r"(B1))

__device__ __forceinline__ void loadW1(uint32_t sb, int ci, int buf, int tid) {
    const char* src = (const char*)g_W1 + (size_t)ci * 64 * 352;
    uint32_t dst = sb + WBUF + buf * 23552;
#pragma unroll
    for (int j = 0; j < 6; j++) {
        int idx = tid + j * 256;
        if (idx < 1408) {
            int row = idx / 22, seg = idx % 22;
            CP16(dst + row * 368 + seg * 16, src + row * 352 + seg * 16);
        }
    }
    CPCOMMIT();
}
__device__ __forceinline__ void loadW2(uint32_t sb, int nc, int buf, int tid) {
    const char* src = (const char*)g_W2 + (size_t)nc * 64 * 512;
    uint32_t dst = sb + W2BUF + buf * 33792;
#pragma unroll
    for (int j = 0; j < 8; j++) {
        int idx = tid + j * 256;
        int row = idx >> 5, seg = idx & 31;
        CP16(dst + row * 528 + seg * 16, src + row * 512 + seg * 16);
    }
    CPCOMMIT();
}

// ---------------- prep kernels ----------------
__global__ void base_kernel(const float* __restrict__ code, const int* __restrict__ dir_idx,
                            const float* __restrict__ dir_emb, const float* __restrict__ ltm_w,
                            const float* __restrict__ ltm_b) {
    int b = blockIdx.x, j = threadIdx.x;
    float acc = ltm_b[j];
    const float* c = code + b * 128;
#pragma unroll 4
    for (int k = 0; k < 128; k++) acc = fmaf(c[k], ltm_w[k * 512 + j], acc);
    const float* dv = dir_emb + dir_idx[b] * 8;
#pragma unroll
    for (int k = 0; k < 8; k++) acc = fmaf(dv[k], ltm_w[(288 + k) * 512 + j], acc);
    g_base[b * 512 + j] = acc;
}

__global__ void prepW1(const float* __restrict__ ltm_w, const float* __restrict__ l0_w) {
    int idx = blockIdx.x * 256 + threadIdx.x;         // 512*176 = 90112
    if (idx >= 512 * 176) return;
    int n = idx / 176, k = idx % 176;
    float v;
    if (k < 160) v = ltm_w[(128 + k) * 512 + n];
    else         v = (n < 256) ? l0_w[(k - 160) * 256 + n] : 0.0f;
    g_W1[idx] = __float2half_rn(v);
}

__global__ void prepW2(const float* __restrict__ l1_w) {
    int idx = blockIdx.x * 256 + threadIdx.x;         // 65536
    int n = idx >> 8, k = idx & 255;
    g_W2[idx] = __float2half_rn(l1_w[k * 256 + n]);
}

// ---------------- main fused kernel ----------------
__global__ __launch_bounds__(256, 1) void main_kernel(
    const float* __restrict__ coords, const float* __restrict__ hs,
    const float* __restrict__ xstat,
    const float* __restrict__ se_w1, const float* __restrict__ se_b1,
    const float* __restrict__ se_w2, const float* __restrict__ se_b2,
    const float* __restrict__ l0_b, const float* __restrict__ l1_b,
    const float* __restrict__ l2_w, const float* __restrict__ l2_b,
    float* __restrict__ out)
{
    extern __shared__ char sh[];
    uint32_t sb = smem_u32(sh);
    const int tid = threadIdx.x, wid = tid >> 5, L = tid & 31;
    const int b = blockIdx.x >> 3, t0 = (blockIdx.x & 7) << 7;
    const int m0 = wid * 16;

    // prefetch first two W1 chunks immediately
    loadW1(sb, 0, 0, tid);
    loadW1(sb, 1, 1, tid);

    // ---- stage A (split fp16 hi/lo) ----
    {   // hs -> k 0..127
        const float4* hs4 = (const float4*)(hs + ((size_t)(b * 1024 + t0)) * 128);
#pragma unroll
        for (int i = 0; i < 16; i++) {
            int idx = tid + i * 256;
            int r = idx >> 5, q = idx & 31;
            float4 v = hs4[r * 32 + q];
            __half h0 = __float2half_rn(v.x), h1 = __float2half_rn(v.y);
            __half h2 = __float2half_rn(v.z), h3 = __float2half_rn(v.w);
            uint32_t off = r * 368 + q * 8;
            *(__half2*)(sh + A_HI + off)     = __halves2half2(h0, h1);
            *(__half2*)(sh + A_HI + off + 4) = __halves2half2(h2, h3);
            *(__half2*)(sh + A_LO + off)     = __halves2half2(__float2half_rn(v.x - __half2float(h0)),
                                                              __float2half_rn(v.y - __half2float(h1)));
            *(__half2*)(sh + A_LO + off + 4) = __halves2half2(__float2half_rn(v.z - __half2float(h2)),
                                                              __float2half_rn(v.w - __half2float(h3)));
        }
    }
    {   // pos -> k 160..175
        const float* crd = coords + (size_t)b * 1024 + t0;
#pragma unroll
        for (int i = 0; i < 8; i++) {
            int idx = tid + i * 256;                  // 0..2047
            int r = idx >> 4, p = idx & 15;
            float ang = crd[r] * (1.25f * (float)(p & 7));
            float v = (p < 8) ? sinf(ang) : cosf(ang);
            __half h = __float2half_rn(v);
            *(__half*)(sh + A_HI + r * 368 + (160 + p) * 2) = h;
            *(__half*)(sh + A_LO + r * 368 + (160 + p) * 2) = __float2half_rn(v - __half2float(h));
        }
    }
    {   // spatial (gelu MLP) -> k 128..159 ; two threads per time row
        int r = tid >> 1, hf = tid & 1;
        float4 xs = *(const float4*)(xstat + ((size_t)(b * 1024 + t0 + r)) * 4);
        float h[16];
#pragma unroll
        for (int c = 0; c < 16; c++) {
            int ci = hf * 16 + c;
            float a = se_b1[ci];
            a = fmaf(xs.x, se_w1[ci], a);       a = fmaf(xs.y, se_w1[32 + ci], a);
            a = fmaf(xs.z, se_w1[64 + ci], a);  a = fmaf(xs.w, se_w1[96 + ci], a);
            h[c] = 0.5f * a * (1.0f + erff(a * 0.7071067811865476f));
        }
#pragma unroll
        for (int k2 = 0; k2 < 32; k2++) {
            float pp = hf ? 0.0f : se_b2[k2];
#pragma unroll
            for (int c = 0; c < 16; c++) pp = fmaf(h[c], se_w2[(hf * 16 + c) * 32 + k2], pp);
            pp += __shfl_xor_sync(0xffffffffu, pp, 1);
            if ((k2 >> 4) == hf) {
                __half hh = __float2half_rn(pp);
                *(__half*)(sh + A_HI + r * 368 + (128 + k2) * 2) = hh;
                *(__half*)(sh + A_LO + r * 368 + (128 + k2) * 2) = __float2half_rn(pp - __half2float(hh));
            }
        }
    }
    {   // biases (per-batch base folded) + l2 weights
        ((float*)(sh + BIAS0))[tid] = g_base[b * 512 + tid] + l0_b[tid];
        ((float*)(sh + BIAS1))[tid] = g_base[b * 512 + 256 + tid] + l1_b[tid];
        ((float*)(sh + L2WS))[tid]  = l2_w[tid];
    }

    // fragment addressing
    const uint32_t aRow  = m0 + (L & 15);
    const uint32_t aColB = (L >> 4) * 16;
    const uint32_t aHiAddr = sb + A_HI + aRow * 368 + aColB;
    const uint32_t aLoAddr = sb + A_LO + aRow * 368 + aColB;
    const uint32_t bRowL = (L & 7) + ((L >> 4) << 3);
    const uint32_t bColB = ((L >> 3) & 1) * 16;
    const uint32_t w1Base = bRowL * 368 + bColB;
    const uint32_t w2Base = bRowL * 528 + bColB;

    float accR[4][8][4];   // mods1 + layer1 accumulators (persistent)
    const float* bias0 = (const float*)(sh + BIAS0);
    const float* bias1 = (const float*)(sh + BIAS1);

    // ---- G1 chunks 0..3 : produce x0 ----
#pragma unroll
    for (int ci = 0; ci < 4; ci++) {
        CPWAIT(1);
        __syncthreads();
        float acc[8][4];
#pragma unroll
        for (int s = 0; s < 8; s++) {
            float b0v = bias0[ci * 64 + s * 8 + 2 * (L & 3)];
            float b1v = bias0[ci * 64 + s * 8 + 2 * (L & 3) + 1];
            acc[s][0] = b0v; acc[s][1] = b1v; acc[s][2] = b0v; acc[s][3] = b1v;
        }
        uint32_t wb = sb + WBUF + (uint32_t)(ci & 1) * 23552 + w1Base;
#pragma unroll
        for (int k = 0; k < 11; k++) {
            uint32_t ah0, ah1, ah2, ah3, al0, al1, al2, al3;
            ldsm4(ah0, ah1, ah2, ah3, aHiAddr + k * 32);
            ldsm4(al0, al1, al2, al3, aLoAddr + k * 32);
#pragma unroll
            for (int s2 = 0; s2 < 4; s2++) {
                uint32_t b0, b1, b2, b3;
                ldsm4(b0, b1, b2, b3, wb + s2 * (16 * 368) + k * 32);
                MMA(acc[2 * s2],     ah0, ah1, ah2, ah3, b0, b1);
                MMA(acc[2 * s2],     al0, al1, al2, al3, b0, b1);
                MMA(acc[2 * s2 + 1], ah0, ah1, ah2, ah3, b2, b3);
                MMA(acc[2 * s2 + 1], al0, al1, al2, al3, b2, b3);
            }
        }
        uint32_t r0 = m0 + (L >> 2);
#pragma unroll
        for (int s = 0; s < 8; s++) {
            uint32_t cb = ci * 64 + s * 8 + 2 * (L & 3);
            *(__half2*)(sh + X0OFF + r0 * 528 + cb * 2) =
                __halves2half2(__float2half_rn(fmaxf(acc[s][0], 0.0f)),
                               __float2half_rn(fmaxf(acc[s][1], 0.0f)));
            *(__half2*)(sh + X0OFF + (r0 + 8) * 528 + cb * 2) =
                __halves2half2(__float2half_rn(fmaxf(acc[s][2], 0.0f)),
                               __float2half_rn(fmaxf(acc[s][3], 0.0f)));
        }
        __syncthreads();
        loadW1(sb, ci + 2, ci & 1, tid);
    }

    // ---- G1 chunks 4..7 : mods1 into registers ----
#pragma unroll
    for (int m = 0; m < 4; m++) {
        CPWAIT(1);
        __syncthreads();
#pragma unroll
        for (int s = 0; s < 8; s++) {
            float b0v = bias1[m * 64 + s * 8 + 2 * (L & 3)];
            float b1v = bias1[m * 64 + s * 8 + 2 * (L & 3) + 1];
            accR[m][s][0] = b0v; accR[m][s][1] = b1v; accR[m][s][2] = b0v; accR[m][s][3] = b1v;
        }
        uint32_t wb = sb + WBUF + (uint32_t)(m & 1) * 23552 + w1Base;
#pragma unroll
        for (int k = 0; k < 11; k++) {
            uint32_t ah0, ah1, ah2, ah3, al0, al1, al2, al3;
            ldsm4(ah0, ah1, ah2, ah3, aHiAddr + k * 32);
            ldsm4(al0, al1, al2, al3, aLoAddr + k * 32);
#pragma unroll
            for (int s2 = 0; s2 < 4; s2++) {
                uint32_t b0, b1, b2, b3;
                ldsm4(b0, b1, b2, b3, wb + s2 * (16 * 368) + k * 32);
                MMA(accR[m][2 * s2],     ah0, ah1, ah2, ah3, b0, b1);
                MMA(accR[m][2 * s2],     al0, al1, al2, al3, b0, b1);
                MMA(accR[m][2 * s2 + 1], ah0, ah1, ah2, ah3, b2, b3);
                MMA(accR[m][2 * s2 + 1], al0, al1, al2, al3, b2, b3);
            }
        }
        __syncthreads();
        if (m < 2) loadW1(sb, m + 6, m & 1, tid);
    }

    // ---- G2 : x0 @ l1, accumulating onto accR ----
    loadW2(sb, 0, 0, tid);   // A region is dead now (post-sync of chunk 7)
    loadW2(sb, 1, 1, tid);
    const uint32_t xAddr = sb + X0OFF + aRow * 528 + aColB;
#pragma unroll
    for (int nc = 0; nc < 4; nc++) {
        CPWAIT(1);
        __syncthreads();
        uint32_t wb = sb + W2BUF + (uint32_t)(nc & 1) * 33792 + w2Base;
#pragma unroll
        for (int k = 0; k < 16; k++) {
            uint32_t a0, a1, a2, a3;
            ldsm4(a0, a1, a2, a3, xAddr + k * 32);
#pragma unroll
            for (int s2 = 0; s2 < 4; s2++) {
                uint32_t b0, b1, b2, b3;
                ldsm4(b0, b1, b2, b3, wb + s2 * (16 * 528) + k * 32);
                MMA(accR[nc][2 * s2],     a0, a1, a2, a3, b0, b1);
                MMA(accR[nc][2 * s2 + 1], a0, a1, a2, a3, b2, b3);
            }
        }
        __syncthreads();
        if (nc < 2) loadW2(sb, nc + 2, nc & 1, tid);
    }

    // ---- final epilogue: out = relu(y1) . l2_w + l2_b ----
    float s0 = 0.0f, s1 = 0.0f;
    const float* lw = (const float*)(sh + L2WS);
#pragma unroll
    for (int m = 0; m < 4; m++)
#pragma unroll
        for (int s = 0; s < 8; s++) {
            int c = m * 64 + s * 8 + 2 * (L & 3);
            float w0 = lw[c], w1 = lw[c + 1];
            s0 += fmaxf(accR[m][s][0], 0.0f) * w0 + fmaxf(accR[m][s][1], 0.0f) * w1;
            s1 += fmaxf(accR[m][s][2], 0.0f) * w0 + fmaxf(accR[m][s][3], 0.0f) * w1;
        }
    s0 += __shfl_xor_sync(0xffffffffu, s0, 1);  s0 += __shfl_xor_sync(0xffffffffu, s0, 2);
    s1 += __shfl_xor_sync(0xffffffffu, s1, 1);  s1 += __shfl_xor_sync(0xffffffffu, s1, 2);
    if ((L & 3) == 0) {
        float lb = l2_b[0];
        int r0 = m0 + (L >> 2);
        out[(size_t)b * 1024 + t0 + r0]     = s0 + lb;
        out[(size_t)b * 1024 + t0 + r0 + 8] = s1 + lb;
    }
}

extern "C" void kernel_launch(void* const* d_in, const int* in_sizes, int n_in,
                              void* d_out, int out_size) {
    const float* coords  = (const float*)d_in[0];
    const float* code    = (const float*)d_in[1];
    const float* hs      = (const float*)d_in[2];
    const float* xstat   = (const float*)d_in[3];
    const int*   dir_idx = (const int*)  d_in[4];
    const float* se_w1   = (const float*)d_in[5];
    const float* se_b1   = (const float*)d_in[6];
    const float* se_w2   = (const float*)d_in[7];
    const float* se_b2   = (const float*)d_in[8];
    const float* dir_emb = (const float*)d_in[9];
    const float* ltm_w   = (const float*)d_in[10];
    const float* ltm_b   = (const float*)d_in[11];
    const float* l0_w    = (const float*)d_in[12];
    const float* l0_b    = (const float*)d_in[13];
    const float* l1_w    = (const float*)d_in[14];
    const float* l1_b    = (const float*)d_in[15];
    const float* l2_w    = (const float*)d_in[16];
    const float* l2_b    = (const float*)d_in[17];
    float* out = (float*)d_out;

    cudaFuncSetAttribute(main_kernel, cudaFuncAttributeMaxDynamicSharedMemorySize, SMEMSZ);

    base_kernel<<<128, 512>>>(code, dir_idx, dir_emb, ltm_w, ltm_b);
    prepW1<<<353, 256>>>(ltm_w, l0_w);
    prepW2<<<256, 256>>>(l1_w);
    main_kernel<<<1024, 256, SMEMSZ>>>(coords, hs, xstat, se_w1, se_b1, se_w2, se_b2,
                                       l0_b, l1_b, l2_w, l2_b, out);
}